// round 8
// baseline (speedup 1.0000x reference)
#include <cuda_runtime.h>
#include <cuda_bf16.h>
#include <cstdint>
#include <cstddef>

// Block-diagonal batched GEMM via tf32 HMMA (mma.sync.m16n8k8).
// Round 8: single-product tf32 replaces the 3-product bf16 split.
//   out[start_g + r, c] = sum_h M_g[r,h] * x[start_g + h, c],  c in [0,10752)

#define NGROUPS 15
#define NCOLS   10752
#define NTILES  37

__constant__ int c_g[NGROUPS]     = {64,128,256,96,160,224,192,288,320,112,80,48,32,16,32};
__constant__ int c_start[NGROUPS] = {0,64,192,448,544,704,928,1120,1408,1728,1840,1920,1968,2000,2016};
__constant__ int c_kpad[NGROUPS]  = {64,128,256,128,192,256,192,320,320,128,128,64,64,64,64};
__constant__ int c_aoff[NGROUPS]  = {0,4096,20480,86016,98304,129024,186368,223232,315392,417792,432128,442368,445440,447488,448512};
// tiles sorted heaviest group (most k-chunks) first for wave balance
__constant__ int c_tileg[NTILES]  = {8,8,8,8,8, 7,7,7,7,7, 2,2,2,2, 5,5,5,5,
                                     4,4,4, 6,6,6, 1,1, 3,3, 9,9, 10,10, 0, 11, 12, 13, 14};
__constant__ int c_tiler[NTILES]  = {0,64,128,192,256, 0,64,128,192,256, 0,64,128,192, 0,64,128,192,
                                     0,64,128, 0,64,128, 0,64, 0,64, 0,64, 0,64, 0, 0, 0, 0};

// Preconverted block matrices: tf32-rounded fp32, K zero-padded.
__device__ float g_Atf[450560];

struct MatPtrs { const float* p[NGROUPS]; };

// ---------------- PTX helpers (compute_103-legal) ----------------
__device__ __forceinline__ uint32_t smem_u32(const void* p) {
    uint32_t a;
    asm("{ .reg .u64 t; cvta.to.shared.u64 t, %1; cvt.u32.u64 %0, t; }" : "=r"(a) : "l"(p));
    return a;
}
__device__ __forceinline__ void cp16(uint32_t dst, const void* src) {
    asm volatile("cp.async.cg.shared.global [%0], [%1], 16;" :: "r"(dst), "l"(src));
}
#define CP_COMMIT() asm volatile("cp.async.commit_group;" ::: "memory")
#define CP_WAIT1()  asm volatile("cp.async.wait_group 1;" ::: "memory")

__device__ __forceinline__ uint32_t f2tf32(float v) {
    uint32_t u;
    asm("cvt.rna.tf32.f32 %0, %1;" : "=r"(u) : "f"(v));
    return u;
}
__device__ __forceinline__ void mma_tf32(float* c, const uint32_t* a, uint32_t b0, uint32_t b1) {
    asm volatile("mma.sync.aligned.m16n8k8.row.col.f32.tf32.tf32.f32 "
        "{%0,%1,%2,%3}, {%4,%5,%6,%7}, {%8,%9}, {%0,%1,%2,%3};"
        : "+f"(c[0]), "+f"(c[1]), "+f"(c[2]), "+f"(c[3])
        : "r"(a[0]), "r"(a[1]), "r"(a[2]), "r"(a[3]), "r"(b0), "r"(b1));
}

// ---------------- prep: round mats to tf32, K zero-padded ----------------
__global__ void conv_mats_kernel(MatPtrs mats) {
    const int idx = blockIdx.x * 256 + threadIdx.x;
    if (idx >= 450560) return;
    int g = 0;
    #pragma unroll
    for (int i = 1; i < NGROUPS; i++) if (idx >= c_aoff[i]) g = i;
    const int local = idx - c_aoff[g];
    const int Kp = c_kpad[g], G = c_g[g];
    const int m = local / Kp;
    const int k = local - m * Kp;
    float v = (k < G) ? mats.p[g][m * G + k] : 0.0f;
    const uint32_t u = f2tf32(v);
    g_Atf[idx] = __uint_as_float(u);
}

// ---------------- main tf32 HMMA kernel ----------------
#define APITCH 36    // floats: 32 k + 4 pad -> conflict-free A frag LDS
#define BPITCH 136   // floats: 128 n + 8 pad -> conflict-free B frag LDS
#define OFF_A  0
#define OFF_B  9216                    // 64 * 36 * 4
#define STAGE_BYTES 26624              // 9216 + 32*136*4
#define SMEM_TOTAL  (2 * STAGE_BYTES)  // 53248 -> 2 CTAs/SM

__global__ __launch_bounds__(256, 2)
void bdiag_tf32_kernel(const float* __restrict__ x, float* __restrict__ out)
{
    extern __shared__ char smem[];
    const uint32_t sb = smem_u32(smem);

    const int tid    = threadIdx.x;
    const int lane   = tid & 31;
    const int wid    = tid >> 5;
    const int warp_m = wid & 1;
    const int warp_n = wid >> 1;

    const int tile  = blockIdx.y;
    const int grp   = c_tileg[tile];
    const int K     = c_g[grp];
    const int Kpad  = c_kpad[grp];
    const int row0  = c_tiler[tile];
    const int col0  = blockIdx.x * 128;
    const int xbase = c_start[grp];

    const float* __restrict__ Ag = g_Atf + c_aoff[grp];

    // A cp.async ownership: 512 slots (64 rows x 8 segs of 16B), 2 per thread.
    const int a_m0 = tid >> 3,          a_m1 = (tid + 256) >> 3;
    const int a_s0 = tid & 7,           a_s1 = a_s0;   // (tid+256)&7 == tid&7
    const bool a_ok0 = (row0 + a_m0) < K;
    const bool a_ok1 = (row0 + a_m1) < K;

    // Zero-prefill invalid A rows once (both stages); never overwritten.
    {
        const uint4 z = make_uint4(0, 0, 0, 0);
        if (!a_ok0) {
            const uint32_t d = a_m0 * (APITCH * 4) + a_s0 * 16;
            *reinterpret_cast<uint4*>(smem + d + OFF_A) = z;
            *reinterpret_cast<uint4*>(smem + d + STAGE_BYTES + OFF_A) = z;
        }
        if (!a_ok1) {
            const uint32_t d = a_m1 * (APITCH * 4) + a_s1 * 16;
            *reinterpret_cast<uint4*>(smem + d + OFF_A) = z;
            *reinterpret_cast<uint4*>(smem + d + STAGE_BYTES + OFF_A) = z;
        }
    }

    // B ownership: 4 float4 per thread; slot idx = tid + j*256
    const int b_k[4]  = { tid >> 5, (tid + 256) >> 5, (tid + 512) >> 5, (tid + 768) >> 5 };
    const int b_c4    = tid & 31;
    const int nch     = Kpad >> 5;

    auto issueA = [&](int ch, uint32_t sbuf) {
        const int kc0 = ch << 5;
        if (a_ok0) {
            cp16(sbuf + a_m0 * (APITCH * 4) + a_s0 * 16,
                 Ag + (size_t)(row0 + a_m0) * Kpad + kc0 + a_s0 * 4);
        }
        if (a_ok1) {
            cp16(sbuf + a_m1 * (APITCH * 4) + a_s1 * 16,
                 Ag + (size_t)(row0 + a_m1) * Kpad + kc0 + a_s1 * 4);
        }
    };
    float4 r[4];
    auto ldgB = [&](int ch) {
        const int kc0 = ch << 5;
        #pragma unroll
        for (int j = 0; j < 4; j++) {
            r[j] = make_float4(0.f, 0.f, 0.f, 0.f);
            if (kc0 + b_k[j] < K)
                r[j] = *reinterpret_cast<const float4*>(
                    x + (size_t)(xbase + kc0 + b_k[j]) * NCOLS + col0 + b_c4 * 4);
        }
    };
    auto convB = [&](uint32_t off) {   // off = byte offset of stage within smem
        #pragma unroll
        for (int j = 0; j < 4; j++) {
            uint4 t;
            t.x = f2tf32(r[j].x);
            t.y = f2tf32(r[j].y);
            t.z = f2tf32(r[j].z);
            t.w = f2tf32(r[j].w);
            *reinterpret_cast<uint4*>(
                smem + off + OFF_B + b_k[j] * (BPITCH * 4) + b_c4 * 16) = t;
        }
    };

    float acc[2][4][4];
    #pragma unroll
    for (int mi = 0; mi < 2; mi++)
        #pragma unroll
        for (int ni = 0; ni < 4; ni++)
            #pragma unroll
            for (int q = 0; q < 4; q++) acc[mi][ni][q] = 0.0f;

    const int lq = lane >> 2;   // 0..7
    const int lr = lane & 3;    // 0..3

    // ---- prologue
    ldgB(0);
    issueA(0, sb);
    CP_COMMIT();
    convB(0);
    if (nch > 1) ldgB(1);

    for (int ch = 0; ch < nch; ch++) {
        if (ch + 1 < nch) issueA(ch + 1, sb + ((ch + 1) & 1) * STAGE_BYTES);
        CP_COMMIT();
        CP_WAIT1();          // A(ch) landed (groups complete in order)
        __syncthreads();     // stage ch fully visible

        const float* sA = reinterpret_cast<const float*>(
            smem + (ch & 1) * STAGE_BYTES + OFF_A);
        const float* sB = reinterpret_cast<const float*>(
            smem + (ch & 1) * STAGE_BYTES + OFF_B);

        #pragma unroll
        for (int ks = 0; ks < 4; ks++) {
            // A fragments: m16n8k8 row-major: a0=(r,c) a1=(r+8,c) a2=(r,c+4) a3=(r+8,c+4)
            uint32_t af[2][4];
            #pragma unroll
            for (int mi = 0; mi < 2; mi++) {
                const int rbase = warp_m * 32 + mi * 16 + lq;
                const int cbase = ks * 8 + lr;
                af[mi][0] = __float_as_uint(sA[rbase * APITCH + cbase]);
                af[mi][1] = __float_as_uint(sA[(rbase + 8) * APITCH + cbase]);
                af[mi][2] = __float_as_uint(sA[rbase * APITCH + cbase + 4]);
                af[mi][3] = __float_as_uint(sA[(rbase + 8) * APITCH + cbase + 4]);
            }
            // B fragments: col-major: b0=(k=lr, n), b1=(k=lr+4, n), n = warp_n*32+ni*8+lq
            uint32_t bf[4][2];
            #pragma unroll
            for (int ni = 0; ni < 4; ni++) {
                const int nn = warp_n * 32 + ni * 8 + lq;
                bf[ni][0] = __float_as_uint(sB[(ks * 8 + lr) * BPITCH + nn]);
                bf[ni][1] = __float_as_uint(sB[(ks * 8 + lr + 4) * BPITCH + nn]);
            }
            #pragma unroll
            for (int mi = 0; mi < 2; mi++)
                #pragma unroll
                for (int ni = 0; ni < 4; ni++)
                    mma_tf32(acc[mi][ni], af[mi], bf[ni][0], bf[ni][1]);
        }

        // convert next chunk's B (regs -> other stage), then refill regs
        if (ch + 1 < nch) convB(((ch + 1) & 1) * STAGE_BYTES);
        if (ch + 2 < nch) ldgB(ch + 2);

        __syncthreads();     // stage reads done + next-stage B STS ordered
    }

    // ---- epilogue: masked float2 stores straight from fragments
    const int rbase = row0 + warp_m * 32 + lq;
    const int cb    = col0 + warp_n * 32 + lr * 2;
    #pragma unroll
    for (int mi = 0; mi < 2; mi++) {
        #pragma unroll
        for (int half = 0; half < 2; half++) {
            const int row = rbase + mi * 16 + half * 8;
            if (row < K) {
                float* dst = out + (size_t)(xbase + row) * NCOLS + cb;
                #pragma unroll
                for (int ni = 0; ni < 4; ni++)
                    *reinterpret_cast<float2*>(dst + ni * 8) =
                        make_float2(acc[mi][ni][half * 2], acc[mi][ni][half * 2 + 1]);
            }
        }
    }
}

extern "C" void kernel_launch(void* const* d_in, const int* in_sizes, int n_in,
                              void* d_out, int out_size)
{
    const float* x = (const float*)d_in[0];
    float* out = (float*)d_out;

    MatPtrs mats;
    for (int i = 0; i < NGROUPS; i++) mats.p[i] = (const float*)d_in[1 + i];

    cudaFuncSetAttribute(bdiag_tf32_kernel,
                         cudaFuncAttributeMaxDynamicSharedMemorySize, SMEM_TOTAL);

    conv_mats_kernel<<<1760, 256>>>(mats);
    bdiag_tf32_kernel<<<dim3(NCOLS / 128, NTILES), 256, SMEM_TOTAL>>>(x, out);
}

// round 9
// speedup vs baseline: 1.6807x; 1.6807x over previous
#include <cuda_runtime.h>
#include <cuda_fp16.h>
#include <cstdint>
#include <cstddef>

// Block-diagonal batched GEMM via fp16 HMMA (mma.sync m16n8k16), asymmetric
// 2-product split: A = Ah + Al (fp16 pair, preconverted), B rounded to fp16.
//   out = (Ah + Al) @ fp16(B);  error ~ A @ (B - fp16(B)) ~ 2e-4 rel.

#define NGROUPS 15
#define NCOLS   10752
#define NTILES  37

__constant__ int c_g[NGROUPS]     = {64,128,256,96,160,224,192,288,320,112,80,48,32,16,32};
__constant__ int c_start[NGROUPS] = {0,64,192,448,544,704,928,1120,1408,1728,1840,1920,1968,2000,2016};
__constant__ int c_kpad[NGROUPS]  = {64,128,256,128,192,256,192,320,320,128,128,64,64,64,64};
__constant__ int c_aoff[NGROUPS]  = {0,4096,20480,86016,98304,129024,186368,223232,315392,417792,432128,442368,445440,447488,448512};
// tiles sorted heaviest group (most k-chunks) first for wave balance
__constant__ int c_tileg[NTILES]  = {8,8,8,8,8, 7,7,7,7,7, 2,2,2,2, 5,5,5,5,
                                     4,4,4, 6,6,6, 1,1, 3,3, 9,9, 10,10, 0, 11, 12, 13, 14};
__constant__ int c_tiler[NTILES]  = {0,64,128,192,256, 0,64,128,192,256, 0,64,128,192, 0,64,128,192,
                                     0,64,128, 0,64,128, 0,64, 0,64, 0,64, 0,64, 0, 0, 0, 0};

// Preconverted block matrices (fp16 hi/lo, zero K-padding), zero-initialized.
__device__ __half g_Ah[450560];
__device__ __half g_Al[450560];

struct MatPtrs { const float* p[NGROUPS]; };

// ---------------- PTX helpers (compute_103-legal) ----------------
__device__ __forceinline__ uint32_t smem_u32(const void* p) {
    uint32_t a;
    asm("{ .reg .u64 t; cvta.to.shared.u64 t, %1; cvt.u32.u64 %0, t; }" : "=r"(a) : "l"(p));
    return a;
}
__device__ __forceinline__ void cp16(uint32_t dst, const void* src) {
    asm volatile("cp.async.cg.shared.global [%0], [%1], 16;" :: "r"(dst), "l"(src));
}
#define CP_COMMIT() asm volatile("cp.async.commit_group;" ::: "memory")
#define CP_WAIT1()  asm volatile("cp.async.wait_group 1;" ::: "memory")

__device__ __forceinline__ void ldsm_x4(uint32_t* r, uint32_t addr) {
    asm volatile("ldmatrix.sync.aligned.m8n8.x4.shared.b16 {%0,%1,%2,%3}, [%4];"
        : "=r"(r[0]), "=r"(r[1]), "=r"(r[2]), "=r"(r[3]) : "r"(addr));
}
__device__ __forceinline__ void ldsm_x4_t(uint32_t* r, uint32_t addr) {
    asm volatile("ldmatrix.sync.aligned.m8n8.x4.trans.shared.b16 {%0,%1,%2,%3}, [%4];"
        : "=r"(r[0]), "=r"(r[1]), "=r"(r[2]), "=r"(r[3]) : "r"(addr));
}
__device__ __forceinline__ void mma_f16(float* c, const uint32_t* a, uint32_t b0, uint32_t b1) {
    asm volatile("mma.sync.aligned.m16n8k16.row.col.f32.f16.f16.f32 "
        "{%0,%1,%2,%3}, {%4,%5,%6,%7}, {%8,%9}, {%0,%1,%2,%3};"
        : "+f"(c[0]), "+f"(c[1]), "+f"(c[2]), "+f"(c[3])
        : "r"(a[0]), "r"(a[1]), "r"(a[2]), "r"(a[3]), "r"(b0), "r"(b1));
}

// ---------------- prep: split mats into fp16 hi/lo (K zero-padded) ----------------
__global__ void conv_mats_kernel(MatPtrs mats) {
    const int idx = blockIdx.x * 256 + threadIdx.x;
    if (idx >= 450560) return;
    int g = 0;
    #pragma unroll
    for (int i = 1; i < NGROUPS; i++) if (idx >= c_aoff[i]) g = i;
    const int local = idx - c_aoff[g];
    const int Kp = c_kpad[g], G = c_g[g];
    const int m = local / Kp;
    const int k = local - m * Kp;
    float v = (k < G) ? mats.p[g][m * G + k] : 0.0f;
    __half h = __float2half_rn(v);
    g_Ah[idx] = h;
    g_Al[idx] = __float2half_rn(v - __half2float(h));
}

// ---------------- main fp16 HMMA kernel ----------------
#define APITCH 40    // 32 k + 8 pad fp16 -> 80B rows
#define BPITCH 136   // 128 n + 8 pad fp16 -> 272B rows
#define OFF_AH 0
#define OFF_AL 5120
#define OFF_B  10240
#define STAGE_BYTES 18944              // 10240 + 32*272
#define SMEM_TOTAL  (2 * STAGE_BYTES)  // 37888 -> 2 CTAs/SM

__global__ __launch_bounds__(256, 2)
void bdiag_hmma_kernel(const float* __restrict__ x, float* __restrict__ out)
{
    extern __shared__ char smem[];
    const uint32_t sb = smem_u32(smem);

    const int tid    = threadIdx.x;
    const int lane   = tid & 31;
    const int wid    = tid >> 5;
    const int warp_m = wid & 1;
    const int warp_n = wid >> 1;

    const int tile  = blockIdx.y;
    const int grp   = c_tileg[tile];
    const int K     = c_g[grp];
    const int Kpad  = c_kpad[grp];
    const int row0  = c_tiler[tile];
    const int col0  = blockIdx.x * 128;
    const int xbase = c_start[grp];

    const __half* __restrict__ Ahg = g_Ah + c_aoff[grp];
    const __half* __restrict__ Alg = g_Al + c_aoff[grp];

    // A cp.async ownership
    const int a_m   = tid >> 2;
    const int a_seg = tid & 3;
    const bool a_ok = (row0 + a_m) < K;

    // Zero-prefill invalid A rows once (both stages, hi+lo); never overwritten.
    if (!a_ok) {
        const uint32_t d = a_m * 80 + a_seg * 16;
        const uint4 z = make_uint4(0, 0, 0, 0);
        *reinterpret_cast<uint4*>(smem + d + OFF_AH) = z;
        *reinterpret_cast<uint4*>(smem + d + OFF_AL) = z;
        *reinterpret_cast<uint4*>(smem + d + STAGE_BYTES + OFF_AH) = z;
        *reinterpret_cast<uint4*>(smem + d + STAGE_BYTES + OFF_AL) = z;
    }

    // B ownership: 4 float4 per thread; slot idx = tid + j*256
    const int b_k[4]  = { tid >> 5, (tid + 256) >> 5, (tid + 512) >> 5, (tid + 768) >> 5 };
    const int b_c4    = tid & 31;   // same low 5 bits for all j
    const int nch     = Kpad >> 5;

    auto issueA = [&](int ch, uint32_t sbuf) {
        if (a_ok) {
            const size_t go = (size_t)(row0 + a_m) * Kpad + (ch << 5) + a_seg * 8;
            const uint32_t d = sbuf + a_m * 80 + a_seg * 16;
            cp16(d + OFF_AH, Ahg + go);
            cp16(d + OFF_AL, Alg + go);
        }
    };
    float4 r[4];
    auto ldgB = [&](int ch) {
        const int kc0 = ch << 5;
        #pragma unroll
        for (int j = 0; j < 4; j++) {
            r[j] = make_float4(0.f, 0.f, 0.f, 0.f);
            if (kc0 + b_k[j] < K)
                r[j] = *reinterpret_cast<const float4*>(
                    x + (size_t)(xbase + kc0 + b_k[j]) * NCOLS + col0 + b_c4 * 4);
        }
    };
    auto convB = [&](uint32_t off) {   // off = stage byte offset within smem
        #pragma unroll
        for (int j = 0; j < 4; j++) {
            __half2 h01 = __floats2half2_rn(r[j].x, r[j].y);
            __half2 h23 = __floats2half2_rn(r[j].z, r[j].w);
            uint2 u;
            u.x = *reinterpret_cast<uint32_t*>(&h01);
            u.y = *reinterpret_cast<uint32_t*>(&h23);
            // 4 fp16 = 8 bytes per thread-slot
            *reinterpret_cast<uint2*>(smem + off + OFF_B + b_k[j] * 272 + b_c4 * 8) = u;
        }
    };

    float acc[2][4][4];
    #pragma unroll
    for (int mi = 0; mi < 2; mi++)
        #pragma unroll
        for (int ni = 0; ni < 4; ni++)
            #pragma unroll
            for (int q = 0; q < 4; q++) acc[mi][ni][q] = 0.0f;

    const int lr = lane & 15;
    const int lc = lane >> 4;

    // ---- prologue: chunk 0 staged, chunk 1 fp32 in regs
    ldgB(0);
    issueA(0, sb);
    CP_COMMIT();
    convB(0);
    if (nch > 1) ldgB(1);

    for (int ch = 0; ch < nch; ch++) {
        if (ch + 1 < nch) issueA(ch + 1, sb + ((ch + 1) & 1) * STAGE_BYTES);
        CP_COMMIT();
        CP_WAIT1();          // A(ch) landed (groups complete in order)
        __syncthreads();     // stage ch fully visible to all warps

        const uint32_t sbase = sb + (ch & 1) * STAGE_BYTES;
        #pragma unroll
        for (int ks = 0; ks < 2; ks++) {
            uint32_t ah[2][4], al[2][4];
            #pragma unroll
            for (int mi = 0; mi < 2; mi++) {
                const uint32_t ao = sbase + OFF_AH +
                    ((warp_m * 32 + mi * 16 + lr) * APITCH + ks * 16 + lc * 8) * 2;
                ldsm_x4(ah[mi], ao);
                ldsm_x4(al[mi], ao + (OFF_AL - OFF_AH));
            }
            uint32_t bf[2][4];
            #pragma unroll
            for (int p = 0; p < 2; p++) {
                const uint32_t bo = sbase + OFF_B +
                    ((ks * 16 + lr) * BPITCH + warp_n * 32 + p * 16 + lc * 8) * 2;
                ldsm_x4_t(bf[p], bo);
            }
            #pragma unroll
            for (int mi = 0; mi < 2; mi++)
                #pragma unroll
                for (int ni = 0; ni < 4; ni++) {
                    const int p = ni >> 1, s = (ni & 1) * 2;
                    mma_f16(acc[mi][ni], ah[mi], bf[p][s], bf[p][s + 1]);
                    mma_f16(acc[mi][ni], al[mi], bf[p][s], bf[p][s + 1]);
                }
        }

        // convert next chunk's B (regs -> other stage), then refill regs
        if (ch + 1 < nch) convB(((ch + 1) & 1) * STAGE_BYTES);
        if (ch + 2 < nch) ldgB(ch + 2);

        __syncthreads();     // stage reads done + next-stage B STS ordered
    }

    // ---- epilogue: masked float2 stores straight from fragments
    const int rbase = row0 + warp_m * 32 + (lane >> 2);
    const int cb    = col0 + warp_n * 32 + (lane & 3) * 2;
    #pragma unroll
    for (int mi = 0; mi < 2; mi++) {
        #pragma unroll
        for (int half = 0; half < 2; half++) {
            const int row = rbase + mi * 16 + half * 8;
            if (row < K) {
                float* dst = out + (size_t)(xbase + row) * NCOLS + cb;
                #pragma unroll
                for (int ni = 0; ni < 4; ni++)
                    *reinterpret_cast<float2*>(dst + ni * 8) =
                        make_float2(acc[mi][ni][half * 2], acc[mi][ni][half * 2 + 1]);
            }
        }
    }
}

extern "C" void kernel_launch(void* const* d_in, const int* in_sizes, int n_in,
                              void* d_out, int out_size)
{
    const float* x = (const float*)d_in[0];
    float* out = (float*)d_out;

    MatPtrs mats;
    for (int i = 0; i < NGROUPS; i++) mats.p[i] = (const float*)d_in[1 + i];

    cudaFuncSetAttribute(bdiag_hmma_kernel,
                         cudaFuncAttributeMaxDynamicSharedMemorySize, SMEM_TOTAL);

    conv_mats_kernel<<<1760, 256>>>(mats);
    bdiag_hmma_kernel<<<dim3(NCOLS / 128, NTILES), 256, SMEM_TOTAL>>>(x, out);
}

// round 10
// speedup vs baseline: 2.0147x; 1.1987x over previous
#include <cuda_runtime.h>
#include <cuda_fp16.h>
#include <cstdint>
#include <cstddef>

// Block-diagonal batched GEMM via fp16 HMMA (mma.sync m16n8k16), single
// product: A and B both rounded to fp16 (11-bit significand each; measured
// tf32 proxy for two-operand rounding error = 2.94e-4 << 1e-3 threshold).
//   out[start_g + r, c] = sum_h M_g[r,h] * x[start_g + h, c],  c in [0,10752)

#define NGROUPS 15
#define NCOLS   10752
#define NTILES  37

__constant__ int c_g[NGROUPS]     = {64,128,256,96,160,224,192,288,320,112,80,48,32,16,32};
__constant__ int c_start[NGROUPS] = {0,64,192,448,544,704,928,1120,1408,1728,1840,1920,1968,2000,2016};
__constant__ int c_kpad[NGROUPS]  = {64,128,256,128,192,256,192,320,320,128,128,64,64,64,64};
__constant__ int c_aoff[NGROUPS]  = {0,4096,20480,86016,98304,129024,186368,223232,315392,417792,432128,442368,445440,447488,448512};
// tiles sorted heaviest group (most k-chunks) first for wave balance
__constant__ int c_tileg[NTILES]  = {8,8,8,8,8, 7,7,7,7,7, 2,2,2,2, 5,5,5,5,
                                     4,4,4, 6,6,6, 1,1, 3,3, 9,9, 10,10, 0, 11, 12, 13, 14};
__constant__ int c_tiler[NTILES]  = {0,64,128,192,256, 0,64,128,192,256, 0,64,128,192, 0,64,128,192,
                                     0,64,128, 0,64,128, 0,64, 0,64, 0,64, 0,64, 0, 0, 0, 0};

// Preconverted block matrices (fp16, zero K-padding), zero-initialized.
__device__ __half g_A[450560];

struct MatPtrs { const float* p[NGROUPS]; };

// ---------------- PTX helpers (compute_103-legal) ----------------
__device__ __forceinline__ uint32_t smem_u32(const void* p) {
    uint32_t a;
    asm("{ .reg .u64 t; cvta.to.shared.u64 t, %1; cvt.u32.u64 %0, t; }" : "=r"(a) : "l"(p));
    return a;
}
__device__ __forceinline__ void cp16(uint32_t dst, const void* src) {
    asm volatile("cp.async.cg.shared.global [%0], [%1], 16;" :: "r"(dst), "l"(src));
}
#define CP_COMMIT() asm volatile("cp.async.commit_group;" ::: "memory")
#define CP_WAIT1()  asm volatile("cp.async.wait_group 1;" ::: "memory")

__device__ __forceinline__ void ldsm_x4(uint32_t* r, uint32_t addr) {
    asm volatile("ldmatrix.sync.aligned.m8n8.x4.shared.b16 {%0,%1,%2,%3}, [%4];"
        : "=r"(r[0]), "=r"(r[1]), "=r"(r[2]), "=r"(r[3]) : "r"(addr));
}
__device__ __forceinline__ void ldsm_x4_t(uint32_t* r, uint32_t addr) {
    asm volatile("ldmatrix.sync.aligned.m8n8.x4.trans.shared.b16 {%0,%1,%2,%3}, [%4];"
        : "=r"(r[0]), "=r"(r[1]), "=r"(r[2]), "=r"(r[3]) : "r"(addr));
}
__device__ __forceinline__ void mma_f16(float* c, const uint32_t* a, uint32_t b0, uint32_t b1) {
    asm volatile("mma.sync.aligned.m16n8k16.row.col.f32.f16.f16.f32 "
        "{%0,%1,%2,%3}, {%4,%5,%6,%7}, {%8,%9}, {%0,%1,%2,%3};"
        : "+f"(c[0]), "+f"(c[1]), "+f"(c[2]), "+f"(c[3])
        : "r"(a[0]), "r"(a[1]), "r"(a[2]), "r"(a[3]), "r"(b0), "r"(b1));
}

// ---------------- prep: round mats to fp16 (K zero-padded) ----------------
__global__ void conv_mats_kernel(MatPtrs mats) {
    const int idx = blockIdx.x * 256 + threadIdx.x;
    if (idx >= 450560) return;
    int g = 0;
    #pragma unroll
    for (int i = 1; i < NGROUPS; i++) if (idx >= c_aoff[i]) g = i;
    const int local = idx - c_aoff[g];
    const int Kp = c_kpad[g], G = c_g[g];
    const int m = local / Kp;
    const int k = local - m * Kp;
    float v = (k < G) ? mats.p[g][m * G + k] : 0.0f;
    g_A[idx] = __float2half_rn(v);
}

// ---------------- main fp16 HMMA kernel ----------------
#define APITCH 40    // 32 k + 8 pad fp16 -> 80B rows
#define BPITCH 136   // 128 n + 8 pad fp16 -> 272B rows
#define OFF_A  0
#define OFF_B  5120
#define STAGE_BYTES 13824              // 5120 + 32*272
#define SMEM_TOTAL  (2 * STAGE_BYTES)  // 27648 -> 2 CTAs/SM easily

__global__ __launch_bounds__(256, 2)
void bdiag_hmma_kernel(const float* __restrict__ x, float* __restrict__ out)
{
    extern __shared__ char smem[];
    const uint32_t sb = smem_u32(smem);

    const int tid    = threadIdx.x;
    const int lane   = tid & 31;
    const int wid    = tid >> 5;
    const int warp_m = wid & 1;
    const int warp_n = wid >> 1;

    const int tile  = blockIdx.y;
    const int grp   = c_tileg[tile];
    const int K     = c_g[grp];
    const int Kpad  = c_kpad[grp];
    const int row0  = c_tiler[tile];
    const int col0  = blockIdx.x * 128;
    const int xbase = c_start[grp];

    const __half* __restrict__ Ag = g_A + c_aoff[grp];

    // A cp.async ownership: 256 slots (64 rows x 4 segs of 16B), 1 per thread.
    const int a_m   = tid >> 2;
    const int a_seg = tid & 3;
    const bool a_ok = (row0 + a_m) < K;

    // Zero-prefill invalid A rows once (both stages); never overwritten.
    if (!a_ok) {
        const uint32_t d = a_m * 80 + a_seg * 16;
        const uint4 z = make_uint4(0, 0, 0, 0);
        *reinterpret_cast<uint4*>(smem + d + OFF_A) = z;
        *reinterpret_cast<uint4*>(smem + d + STAGE_BYTES + OFF_A) = z;
    }

    // B ownership: 4 float4 per thread; slot idx = tid + j*256
    const int b_k[4]  = { tid >> 5, (tid + 256) >> 5, (tid + 512) >> 5, (tid + 768) >> 5 };
    const int b_c4    = tid & 31;   // same low 5 bits for all j
    const int nch     = Kpad >> 5;

    auto issueA = [&](int ch, uint32_t sbuf) {
        if (a_ok) {
            const size_t go = (size_t)(row0 + a_m) * Kpad + (ch << 5) + a_seg * 8;
            cp16(sbuf + a_m * 80 + a_seg * 16 + OFF_A, Ag + go);
        }
    };
    float4 r[4];
    auto ldgB = [&](int ch) {
        const int kc0 = ch << 5;
        #pragma unroll
        for (int j = 0; j < 4; j++) {
            r[j] = make_float4(0.f, 0.f, 0.f, 0.f);
            if (kc0 + b_k[j] < K)
                r[j] = *reinterpret_cast<const float4*>(
                    x + (size_t)(xbase + kc0 + b_k[j]) * NCOLS + col0 + b_c4 * 4);
        }
    };
    auto convB = [&](uint32_t off) {   // off = stage byte offset within smem
        #pragma unroll
        for (int j = 0; j < 4; j++) {
            __half2 h01 = __floats2half2_rn(r[j].x, r[j].y);
            __half2 h23 = __floats2half2_rn(r[j].z, r[j].w);
            uint2 u;
            u.x = *reinterpret_cast<uint32_t*>(&h01);
            u.y = *reinterpret_cast<uint32_t*>(&h23);
            // 4 fp16 = 8 bytes per thread-slot
            *reinterpret_cast<uint2*>(smem + off + OFF_B + b_k[j] * 272 + b_c4 * 8) = u;
        }
    };

    float acc[2][4][4];
    #pragma unroll
    for (int mi = 0; mi < 2; mi++)
        #pragma unroll
        for (int ni = 0; ni < 4; ni++)
            #pragma unroll
            for (int q = 0; q < 4; q++) acc[mi][ni][q] = 0.0f;

    const int lr = lane & 15;
    const int lc = lane >> 4;

    // ---- prologue: chunk 0 staged, chunk 1 fp32 in regs
    ldgB(0);
    issueA(0, sb);
    CP_COMMIT();
    convB(0);
    if (nch > 1) ldgB(1);

    for (int ch = 0; ch < nch; ch++) {
        if (ch + 1 < nch) issueA(ch + 1, sb + ((ch + 1) & 1) * STAGE_BYTES);
        CP_COMMIT();
        CP_WAIT1();          // A(ch) landed (groups complete in order)
        __syncthreads();     // stage ch fully visible to all warps

        const uint32_t sbase = sb + (ch & 1) * STAGE_BYTES;
        #pragma unroll
        for (int ks = 0; ks < 2; ks++) {
            uint32_t af[2][4];
            #pragma unroll
            for (int mi = 0; mi < 2; mi++) {
                const uint32_t ao = sbase + OFF_A +
                    ((warp_m * 32 + mi * 16 + lr) * APITCH + ks * 16 + lc * 8) * 2;
                ldsm_x4(af[mi], ao);
            }
            uint32_t bf[2][4];
            #pragma unroll
            for (int p = 0; p < 2; p++) {
                const uint32_t bo = sbase + OFF_B +
                    ((ks * 16 + lr) * BPITCH + warp_n * 32 + p * 16 + lc * 8) * 2;
                ldsm_x4_t(bf[p], bo);
            }
            #pragma unroll
            for (int mi = 0; mi < 2; mi++)
                #pragma unroll
                for (int ni = 0; ni < 4; ni++) {
                    const int p = ni >> 1, s = (ni & 1) * 2;
                    mma_f16(acc[mi][ni], af[mi], bf[p][s], bf[p][s + 1]);
                }
        }

        // convert next chunk's B (regs -> other stage), then refill regs
        if (ch + 1 < nch) convB(((ch + 1) & 1) * STAGE_BYTES);
        if (ch + 2 < nch) ldgB(ch + 2);

        __syncthreads();     // stage reads done + next-stage B STS ordered
    }

    // ---- epilogue: masked float2 stores straight from fragments
    const int rbase = row0 + warp_m * 32 + (lane >> 2);
    const int cb    = col0 + warp_n * 32 + (lane & 3) * 2;
    #pragma unroll
    for (int mi = 0; mi < 2; mi++) {
        #pragma unroll
        for (int half = 0; half < 2; half++) {
            const int row = rbase + mi * 16 + half * 8;
            if (row < K) {
                float* dst = out + (size_t)(xbase + row) * NCOLS + cb;
                #pragma unroll
                for (int ni = 0; ni < 4; ni++)
                    *reinterpret_cast<float2*>(dst + ni * 8) =
                        make_float2(acc[mi][ni][half * 2], acc[mi][ni][half * 2 + 1]);
            }
        }
    }
}

extern "C" void kernel_launch(void* const* d_in, const int* in_sizes, int n_in,
                              void* d_out, int out_size)
{
    const float* x = (const float*)d_in[0];
    float* out = (float*)d_out;

    MatPtrs mats;
    for (int i = 0; i < NGROUPS; i++) mats.p[i] = (const float*)d_in[1 + i];

    cudaFuncSetAttribute(bdiag_hmma_kernel,
                         cudaFuncAttributeMaxDynamicSharedMemorySize, SMEM_TOTAL);

    conv_mats_kernel<<<1760, 256>>>(mats);
    bdiag_hmma_kernel<<<dim3(NCOLS / 128, NTILES), 256, SMEM_TOTAL>>>(x, out);
}

// round 11
// speedup vs baseline: 2.1167x; 1.0506x over previous
#include <cuda_runtime.h>
#include <cuda_fp16.h>
#include <cstdint>
#include <cstddef>

// Block-diagonal batched GEMM via fp16 HMMA (mma.sync m16n8k16), single
// product (A, B both fp16-rounded; measured rel_err 2.94e-4 < 1e-3).
// Round 11: 128x64 tiles (halves B conversion redundancy), BK=64 (halves
// syncs), explicit last-chunk wait (nch==1 safe).

#define NGROUPS 15
#define NCOLS   10752
#define NTILES  23

__constant__ int c_g[NGROUPS]     = {64,128,256,96,160,224,192,288,320,112,80,48,32,16,32};
__constant__ int c_start[NGROUPS] = {0,64,192,448,544,704,928,1120,1408,1728,1840,1920,1968,2000,2016};
__constant__ int c_kpad[NGROUPS]  = {64,128,256,128,192,256,192,320,320,128,128,64,64,64,64};
__constant__ int c_aoff[NGROUPS]  = {0,4096,20480,86016,98304,129024,186368,223232,315392,417792,432128,442368,445440,447488,448512};
// 128-row tiles, heaviest groups first
__constant__ int c_tileg[NTILES]  = {8,8,8, 7,7,7, 2,2, 5,5, 4,4, 6,6, 1, 3, 9, 10, 0, 11, 12, 13, 14};
__constant__ int c_tiler[NTILES]  = {0,128,256, 0,128,256, 0,128, 0,128, 0,128, 0,128, 0,0,0,0,0,0,0,0,0};

// Preconverted block matrices (fp16, zero K-padding), zero-initialized.
__device__ __half g_A[450560];

struct MatPtrs { const float* p[NGROUPS]; };

// ---------------- PTX helpers (compute_103-legal) ----------------
__device__ __forceinline__ uint32_t smem_u32(const void* p) {
    uint32_t a;
    asm("{ .reg .u64 t; cvta.to.shared.u64 t, %1; cvt.u32.u64 %0, t; }" : "=r"(a) : "l"(p));
    return a;
}
__device__ __forceinline__ void cp16(uint32_t dst, const void* src) {
    asm volatile("cp.async.cg.shared.global [%0], [%1], 16;" :: "r"(dst), "l"(src));
}
#define CP_COMMIT() asm volatile("cp.async.commit_group;" ::: "memory")
#define CP_WAIT1()  asm volatile("cp.async.wait_group 1;" ::: "memory")
#define CP_WAIT0()  asm volatile("cp.async.wait_group 0;" ::: "memory")

__device__ __forceinline__ void ldsm_x4(uint32_t* r, uint32_t addr) {
    asm volatile("ldmatrix.sync.aligned.m8n8.x4.shared.b16 {%0,%1,%2,%3}, [%4];"
        : "=r"(r[0]), "=r"(r[1]), "=r"(r[2]), "=r"(r[3]) : "r"(addr));
}
__device__ __forceinline__ void ldsm_x4_t(uint32_t* r, uint32_t addr) {
    asm volatile("ldmatrix.sync.aligned.m8n8.x4.trans.shared.b16 {%0,%1,%2,%3}, [%4];"
        : "=r"(r[0]), "=r"(r[1]), "=r"(r[2]), "=r"(r[3]) : "r"(addr));
}
__device__ __forceinline__ void mma_f16(float* c, const uint32_t* a, uint32_t b0, uint32_t b1) {
    asm volatile("mma.sync.aligned.m16n8k16.row.col.f32.f16.f16.f32 "
        "{%0,%1,%2,%3}, {%4,%5,%6,%7}, {%8,%9}, {%0,%1,%2,%3};"
        : "+f"(c[0]), "+f"(c[1]), "+f"(c[2]), "+f"(c[3])
        : "r"(a[0]), "r"(a[1]), "r"(a[2]), "r"(a[3]), "r"(b0), "r"(b1));
}

// ---------------- prep: round mats to fp16 (K zero-padded) ----------------
__global__ void conv_mats_kernel(MatPtrs mats) {
    const int idx = blockIdx.x * 256 + threadIdx.x;
    if (idx >= 450560) return;
    int g = 0;
    #pragma unroll
    for (int i = 1; i < NGROUPS; i++) if (idx >= c_aoff[i]) g = i;
    const int local = idx - c_aoff[g];
    const int Kp = c_kpad[g], G = c_g[g];
    const int m = local / Kp;
    const int k = local - m * Kp;
    float v = (k < G) ? mats.p[g][m * G + k] : 0.0f;
    g_A[idx] = __float2half_rn(v);
}

// ---------------- main fp16 HMMA kernel ----------------
#define APITCH 72    // fp16: 64 k + 8 pad -> 144B rows (conflict-free)
#define BPITCH 72    // fp16: 64 n + 8 pad -> 144B rows (conflict-free)
#define OFF_A  0
#define OFF_B  18432                   // 128 * 144
#define STAGE_BYTES 27648              // 18432 + 64*144
#define SMEM_TOTAL  (2 * STAGE_BYTES)  // 55296 -> 2 CTAs/SM

__global__ __launch_bounds__(256, 2)
void bdiag_hmma_kernel(const float* __restrict__ x, float* __restrict__ out)
{
    extern __shared__ char smem[];
    const uint32_t sb = smem_u32(smem);

    const int tid    = threadIdx.x;
    const int lane   = tid & 31;
    const int wid    = tid >> 5;
    const int warp_m = wid >> 1;   // 4 warps over M (128 rows)
    const int warp_n = wid & 1;    // 2 warps over N (64 cols)

    const int tile  = blockIdx.y;
    const int grp   = c_tileg[tile];
    const int K     = c_g[grp];
    const int Kpad  = c_kpad[grp];
    const int row0  = c_tiler[tile];
    const int col0  = blockIdx.x * 64;
    const int xbase = c_start[grp];

    const __half* __restrict__ Ag = g_A + c_aoff[grp];

    // A cp.async ownership: 1024 slots (128 rows x 8 segs of 16B), 4/thread.
    int  a_row[4];
    bool a_ok[4];
    const int a_seg = tid & 7;
    #pragma unroll
    for (int j = 0; j < 4; j++) {
        a_row[j] = (tid >> 3) + j * 32;
        a_ok[j]  = (row0 + a_row[j]) < K;
        if (!a_ok[j]) {   // zero-prefill masked rows, both stages
            const uint32_t d = a_row[j] * 144 + a_seg * 16;
            const uint4 z = make_uint4(0, 0, 0, 0);
            *reinterpret_cast<uint4*>(smem + d + OFF_A) = z;
            *reinterpret_cast<uint4*>(smem + d + STAGE_BYTES + OFF_A) = z;
        }
    }

    // B ownership: 4 float4/thread; slot idx = tid + j*256; k = idx>>4, c4 = idx&15
    const int b_k0 = tid >> 4;      // + j*16
    const int b_c4 = tid & 15;
    const int nch  = Kpad >> 6;

    auto issueA = [&](int ch, uint32_t sbuf) {
        const int kc0 = ch << 6;
        #pragma unroll
        for (int j = 0; j < 4; j++) {
            if (a_ok[j])
                cp16(sbuf + a_row[j] * 144 + a_seg * 16 + OFF_A,
                     Ag + (size_t)(row0 + a_row[j]) * Kpad + kc0 + a_seg * 8);
        }
    };
    float4 r[4];
    auto ldgB = [&](int ch) {
        const int kc0 = ch << 6;
        #pragma unroll
        for (int j = 0; j < 4; j++) {
            const int k = b_k0 + j * 16;
            r[j] = make_float4(0.f, 0.f, 0.f, 0.f);
            if (kc0 + k < K)
                r[j] = *reinterpret_cast<const float4*>(
                    x + (size_t)(xbase + kc0 + k) * NCOLS + col0 + b_c4 * 4);
        }
    };
    auto convB = [&](uint32_t off) {   // off = stage byte offset within smem
        #pragma unroll
        for (int j = 0; j < 4; j++) {
            __half2 h01 = __floats2half2_rn(r[j].x, r[j].y);
            __half2 h23 = __floats2half2_rn(r[j].z, r[j].w);
            uint2 u;
            u.x = *reinterpret_cast<uint32_t*>(&h01);
            u.y = *reinterpret_cast<uint32_t*>(&h23);
            *reinterpret_cast<uint2*>(
                smem + off + OFF_B + (b_k0 + j * 16) * 144 + b_c4 * 8) = u;
        }
    };

    float acc[2][4][4];
    #pragma unroll
    for (int mi = 0; mi < 2; mi++)
        #pragma unroll
        for (int ni = 0; ni < 4; ni++)
            #pragma unroll
            for (int q = 0; q < 4; q++) acc[mi][ni][q] = 0.0f;

    const int lr = lane & 15;
    const int lc = lane >> 4;

    // ---- prologue
    ldgB(0);
    issueA(0, sb);
    CP_COMMIT();
    convB(0);
    if (nch > 1) ldgB(1);

    for (int ch = 0; ch < nch; ch++) {
        if (ch + 1 < nch) {
            issueA(ch + 1, sb + ((ch + 1) & 1) * STAGE_BYTES);
            CP_COMMIT();
            CP_WAIT1();      // A(ch) landed (in-order group completion)
        } else {
            CP_WAIT0();      // last chunk: drain everything
        }
        __syncthreads();     // stage ch fully visible (A async + B STS)

        const uint32_t sbase = sb + (ch & 1) * STAGE_BYTES;
        #pragma unroll
        for (int ks = 0; ks < 4; ks++) {
            uint32_t af[2][4];
            #pragma unroll
            for (int mi = 0; mi < 2; mi++) {
                const uint32_t ao = sbase + OFF_A +
                    ((warp_m * 32 + mi * 16 + lr) * APITCH + ks * 16 + lc * 8) * 2;
                ldsm_x4(af[mi], ao);
            }
            uint32_t bf[2][4];
            #pragma unroll
            for (int p = 0; p < 2; p++) {
                const uint32_t bo = sbase + OFF_B +
                    ((ks * 16 + lr) * BPITCH + warp_n * 32 + p * 16 + lc * 8) * 2;
                ldsm_x4_t(bf[p], bo);
            }
            #pragma unroll
            for (int mi = 0; mi < 2; mi++)
                #pragma unroll
                for (int ni = 0; ni < 4; ni++) {
                    const int p = ni >> 1, s = (ni & 1) * 2;
                    mma_f16(acc[mi][ni], af[mi], bf[p][s], bf[p][s + 1]);
                }
        }

        // convert next chunk's B (regs -> other stage), then refill regs
        if (ch + 1 < nch) convB(((ch + 1) & 1) * STAGE_BYTES);
        if (ch + 2 < nch) ldgB(ch + 2);

        __syncthreads();     // stage reads done + next-stage B STS ordered
    }

    // ---- epilogue: masked float2 stores straight from fragments
    const int rbase = row0 + warp_m * 32 + (lane >> 2);
    const int cb    = col0 + warp_n * 32 + (lane & 3) * 2;
    #pragma unroll
    for (int mi = 0; mi < 2; mi++) {
        #pragma unroll
        for (int half = 0; half < 2; half++) {
            const int row = rbase + mi * 16 + half * 8;
            if (row < K) {
                float* dst = out + (size_t)(xbase + row) * NCOLS + cb;
                #pragma unroll
                for (int ni = 0; ni < 4; ni++)
                    *reinterpret_cast<float2*>(dst + ni * 8) =
                        make_float2(acc[mi][ni][half * 2], acc[mi][ni][half * 2 + 1]);
            }
        }
    }
}

extern "C" void kernel_launch(void* const* d_in, const int* in_sizes, int n_in,
                              void* d_out, int out_size)
{
    const float* x = (const float*)d_in[0];
    float* out = (float*)d_out;

    MatPtrs mats;
    for (int i = 0; i < NGROUPS; i++) mats.p[i] = (const float*)d_in[1 + i];

    cudaFuncSetAttribute(bdiag_hmma_kernel,
                         cudaFuncAttributeMaxDynamicSharedMemorySize, SMEM_TOTAL);

    conv_mats_kernel<<<1760, 256>>>(mats);
    bdiag_hmma_kernel<<<dim3(NCOLS / 64, NTILES), 256, SMEM_TOTAL>>>(x, out);
}

// round 12
// speedup vs baseline: 2.1806x; 1.0302x over previous
#include <cuda_runtime.h>
#include <cuda_fp16.h>
#include <cstdint>
#include <cstddef>

// Block-diagonal batched GEMM via fp16 HMMA (mma.sync m16n8k16), single
// product (A, B fp16-rounded; measured rel_err 2.94e-4 < 1e-3).
// Round 12: 3 CTAs/SM (launch_bounds reg cap 85) + inline B conversion
// (no live-across-MMA prefetch registers).

#define NGROUPS 15
#define NCOLS   10752
#define NTILES  23

__constant__ int c_g[NGROUPS]     = {64,128,256,96,160,224,192,288,320,112,80,48,32,16,32};
__constant__ int c_start[NGROUPS] = {0,64,192,448,544,704,928,1120,1408,1728,1840,1920,1968,2000,2016};
__constant__ int c_kpad[NGROUPS]  = {64,128,256,128,192,256,192,320,320,128,128,64,64,64,64};
__constant__ int c_aoff[NGROUPS]  = {0,4096,20480,86016,98304,129024,186368,223232,315392,417792,432128,442368,445440,447488,448512};
// 128-row tiles, heaviest groups first
__constant__ int c_tileg[NTILES]  = {8,8,8, 7,7,7, 2,2, 5,5, 4,4, 6,6, 1, 3, 9, 10, 0, 11, 12, 13, 14};
__constant__ int c_tiler[NTILES]  = {0,128,256, 0,128,256, 0,128, 0,128, 0,128, 0,128, 0,0,0,0,0,0,0,0,0};

// Preconverted block matrices (fp16, zero K-padding), zero-initialized.
__device__ __half g_A[450560];

struct MatPtrs { const float* p[NGROUPS]; };

// ---------------- PTX helpers (compute_103-legal) ----------------
__device__ __forceinline__ uint32_t smem_u32(const void* p) {
    uint32_t a;
    asm("{ .reg .u64 t; cvta.to.shared.u64 t, %1; cvt.u32.u64 %0, t; }" : "=r"(a) : "l"(p));
    return a;
}
__device__ __forceinline__ void cp16(uint32_t dst, const void* src) {
    asm volatile("cp.async.cg.shared.global [%0], [%1], 16;" :: "r"(dst), "l"(src));
}
#define CP_COMMIT() asm volatile("cp.async.commit_group;" ::: "memory")
#define CP_WAIT1()  asm volatile("cp.async.wait_group 1;" ::: "memory")
#define CP_WAIT0()  asm volatile("cp.async.wait_group 0;" ::: "memory")

__device__ __forceinline__ void ldsm_x4(uint32_t* r, uint32_t addr) {
    asm volatile("ldmatrix.sync.aligned.m8n8.x4.shared.b16 {%0,%1,%2,%3}, [%4];"
        : "=r"(r[0]), "=r"(r[1]), "=r"(r[2]), "=r"(r[3]) : "r"(addr));
}
__device__ __forceinline__ void ldsm_x4_t(uint32_t* r, uint32_t addr) {
    asm volatile("ldmatrix.sync.aligned.m8n8.x4.trans.shared.b16 {%0,%1,%2,%3}, [%4];"
        : "=r"(r[0]), "=r"(r[1]), "=r"(r[2]), "=r"(r[3]) : "r"(addr));
}
__device__ __forceinline__ void mma_f16(float* c, const uint32_t* a, uint32_t b0, uint32_t b1) {
    asm volatile("mma.sync.aligned.m16n8k16.row.col.f32.f16.f16.f32 "
        "{%0,%1,%2,%3}, {%4,%5,%6,%7}, {%8,%9}, {%0,%1,%2,%3};"
        : "+f"(c[0]), "+f"(c[1]), "+f"(c[2]), "+f"(c[3])
        : "r"(a[0]), "r"(a[1]), "r"(a[2]), "r"(a[3]), "r"(b0), "r"(b1));
}

// ---------------- prep: round mats to fp16 (K zero-padded) ----------------
__global__ void conv_mats_kernel(MatPtrs mats) {
    const int idx = blockIdx.x * 256 + threadIdx.x;
    if (idx >= 450560) return;
    int g = 0;
    #pragma unroll
    for (int i = 1; i < NGROUPS; i++) if (idx >= c_aoff[i]) g = i;
    const int local = idx - c_aoff[g];
    const int Kp = c_kpad[g], G = c_g[g];
    const int m = local / Kp;
    const int k = local - m * Kp;
    float v = (k < G) ? mats.p[g][m * G + k] : 0.0f;
    g_A[idx] = __float2half_rn(v);
}

// ---------------- main fp16 HMMA kernel ----------------
#define APITCH 72    // fp16: 64 k + 8 pad -> 144B rows (conflict-free)
#define BPITCH 72    // fp16: 64 n + 8 pad -> 144B rows (conflict-free)
#define OFF_A  0
#define OFF_B  18432                   // 128 * 144
#define STAGE_BYTES 27648              // 18432 + 64*144
#define SMEM_TOTAL  (2 * STAGE_BYTES)  // 55296 -> 3 CTAs/SM (166KB of 228KB)

__global__ __launch_bounds__(256, 3)
void bdiag_hmma_kernel(const float* __restrict__ x, float* __restrict__ out)
{
    extern __shared__ char smem[];
    const uint32_t sb = smem_u32(smem);

    const int tid    = threadIdx.x;
    const int lane   = tid & 31;
    const int wid    = tid >> 5;
    const int warp_m = wid >> 1;   // 4 warps over M (128 rows)
    const int warp_n = wid & 1;    // 2 warps over N (64 cols)

    const int tile  = blockIdx.y;
    const int grp   = c_tileg[tile];
    const int K     = c_g[grp];
    const int Kpad  = c_kpad[grp];
    const int row0  = c_tiler[tile];
    const int col0  = blockIdx.x * 64;
    const int xbase = c_start[grp];

    const __half* __restrict__ Ag = g_A + c_aoff[grp];

    // A cp.async ownership: 1024 slots (128 rows x 8 segs of 16B), 4/thread.
    const int a_seg = tid & 7;
    const int a_r0  = tid >> 3;    // + j*32
    #pragma unroll
    for (int j = 0; j < 4; j++) {
        if (row0 + a_r0 + j * 32 >= K) {   // zero-prefill masked rows, both stages
            const uint32_t d = (a_r0 + j * 32) * 144 + a_seg * 16;
            const uint4 z = make_uint4(0, 0, 0, 0);
            *reinterpret_cast<uint4*>(smem + d + OFF_A) = z;
            *reinterpret_cast<uint4*>(smem + d + STAGE_BYTES + OFF_A) = z;
        }
    }

    // B ownership: 4 slots/thread; slot idx = tid + j*256; k = idx>>4, c4 = idx&15
    const int b_k0 = tid >> 4;      // + j*16
    const int b_c4 = tid & 15;
    const int nch  = Kpad >> 6;

    auto issueA = [&](int ch, uint32_t sbuf) {
        const int kc0 = ch << 6;
        #pragma unroll
        for (int j = 0; j < 4; j++) {
            const int rr = a_r0 + j * 32;
            if (row0 + rr < K)
                cp16(sbuf + rr * 144 + a_seg * 16 + OFF_A,
                     Ag + (size_t)(row0 + rr) * Kpad + kc0 + a_seg * 8);
        }
    };
    // Inline B load+convert+store (short-lived temps, MLP=2)
    auto convLoadB = [&](int ch, uint32_t off) {
        const int kc0 = ch << 6;
        #pragma unroll
        for (int jj = 0; jj < 2; jj++) {
            float4 v0 = make_float4(0.f, 0.f, 0.f, 0.f), v1 = v0;
            const int k0 = b_k0 + (jj * 2) * 16;
            const int k1 = b_k0 + (jj * 2 + 1) * 16;
            if (kc0 + k0 < K)
                v0 = *reinterpret_cast<const float4*>(
                    x + (size_t)(xbase + kc0 + k0) * NCOLS + col0 + b_c4 * 4);
            if (kc0 + k1 < K)
                v1 = *reinterpret_cast<const float4*>(
                    x + (size_t)(xbase + kc0 + k1) * NCOLS + col0 + b_c4 * 4);
            __half2 a01 = __floats2half2_rn(v0.x, v0.y);
            __half2 a23 = __floats2half2_rn(v0.z, v0.w);
            __half2 b01 = __floats2half2_rn(v1.x, v1.y);
            __half2 b23 = __floats2half2_rn(v1.z, v1.w);
            uint2 ua, ub;
            ua.x = *reinterpret_cast<uint32_t*>(&a01);
            ua.y = *reinterpret_cast<uint32_t*>(&a23);
            ub.x = *reinterpret_cast<uint32_t*>(&b01);
            ub.y = *reinterpret_cast<uint32_t*>(&b23);
            *reinterpret_cast<uint2*>(smem + off + OFF_B + k0 * 144 + b_c4 * 8) = ua;
            *reinterpret_cast<uint2*>(smem + off + OFF_B + k1 * 144 + b_c4 * 8) = ub;
        }
    };

    float acc[2][4][4];
    #pragma unroll
    for (int mi = 0; mi < 2; mi++)
        #pragma unroll
        for (int ni = 0; ni < 4; ni++)
            #pragma unroll
            for (int q = 0; q < 4; q++) acc[mi][ni][q] = 0.0f;

    const int lr = lane & 15;
    const int lc = lane >> 4;

    // ---- prologue: stage 0 (A async, B inline)
    issueA(0, sb);
    CP_COMMIT();
    convLoadB(0, 0);

    for (int ch = 0; ch < nch; ch++) {
        if (ch + 1 < nch) {
            issueA(ch + 1, sb + ((ch + 1) & 1) * STAGE_BYTES);
            CP_COMMIT();
            CP_WAIT1();      // A(ch) landed (in-order group completion)
        } else {
            CP_WAIT0();      // last chunk: drain everything
        }
        __syncthreads();     // stage ch fully visible (A async + B STS)

        const uint32_t sbase = sb + (ch & 1) * STAGE_BYTES;
        #pragma unroll
        for (int ks = 0; ks < 4; ks++) {
            uint32_t af[2][4];
            #pragma unroll
            for (int mi = 0; mi < 2; mi++) {
                const uint32_t ao = sbase + OFF_A +
                    ((warp_m * 32 + mi * 16 + lr) * APITCH + ks * 16 + lc * 8) * 2;
                ldsm_x4(af[mi], ao);
            }
            uint32_t bf[2][4];
            #pragma unroll
            for (int p = 0; p < 2; p++) {
                const uint32_t bo = sbase + OFF_B +
                    ((ks * 16 + lr) * BPITCH + warp_n * 32 + p * 16 + lc * 8) * 2;
                ldsm_x4_t(bf[p], bo);
            }
            #pragma unroll
            for (int mi = 0; mi < 2; mi++)
                #pragma unroll
                for (int ni = 0; ni < 4; ni++) {
                    const int p = ni >> 1, s = (ni & 1) * 2;
                    mma_f16(acc[mi][ni], af[mi], bf[p][s], bf[p][s + 1]);
                }
        }

        // inline load+convert next chunk's B into the other stage
        if (ch + 1 < nch) convLoadB(ch + 1, ((ch + 1) & 1) * STAGE_BYTES);

        __syncthreads();     // stage reads done + next-stage B STS ordered
    }

    // ---- epilogue: masked float2 stores straight from fragments
    const int rbase = row0 + warp_m * 32 + (lane >> 2);
    const int cb    = col0 + warp_n * 32 + (lane & 3) * 2;
    #pragma unroll
    for (int mi = 0; mi < 2; mi++) {
        #pragma unroll
        for (int half = 0; half < 2; half++) {
            const int row = rbase + mi * 16 + half * 8;
            if (row < K) {
                float* dst = out + (size_t)(xbase + row) * NCOLS + cb;
                #pragma unroll
                for (int ni = 0; ni < 4; ni++)
                    *reinterpret_cast<float2*>(dst + ni * 8) =
                        make_float2(acc[mi][ni][half * 2], acc[mi][ni][half * 2 + 1]);
            }
        }
    }
}

extern "C" void kernel_launch(void* const* d_in, const int* in_sizes, int n_in,
                              void* d_out, int out_size)
{
    const float* x = (const float*)d_in[0];
    float* out = (float*)d_out;

    MatPtrs mats;
    for (int i = 0; i < NGROUPS; i++) mats.p[i] = (const float*)d_in[1 + i];

    cudaFuncSetAttribute(bdiag_hmma_kernel,
                         cudaFuncAttributeMaxDynamicSharedMemorySize, SMEM_TOTAL);

    conv_mats_kernel<<<1760, 256>>>(mats);
    bdiag_hmma_kernel<<<dim3(NCOLS / 64, NTILES), 256, SMEM_TOTAL>>>(x, out);
}

// round 13
// speedup vs baseline: 2.2585x; 1.0357x over previous
#include <cuda_runtime.h>
#include <cuda_fp16.h>
#include <cstdint>
#include <cstddef>

// Block-diagonal batched GEMM via fp16 HMMA (mma.sync m16n8k16), single
// product (A, B fp16-rounded; measured rel_err 2.94e-4 < 1e-3).
// Round 13: 128x128 tiles (0.77x L1 bytes/output), BK=64, 2 CTAs/SM.

#define NGROUPS 15
#define NCOLS   10752
#define NTILES  23

__constant__ int c_g[NGROUPS]     = {64,128,256,96,160,224,192,288,320,112,80,48,32,16,32};
__constant__ int c_start[NGROUPS] = {0,64,192,448,544,704,928,1120,1408,1728,1840,1920,1968,2000,2016};
__constant__ int c_kpad[NGROUPS]  = {64,128,256,128,192,256,192,320,320,128,128,64,64,64,64};
__constant__ int c_aoff[NGROUPS]  = {0,4096,20480,86016,98304,129024,186368,223232,315392,417792,432128,442368,445440,447488,448512};
// 128-row tiles, heaviest groups first
__constant__ int c_tileg[NTILES]  = {8,8,8, 7,7,7, 2,2, 5,5, 4,4, 6,6, 1, 3, 9, 10, 0, 11, 12, 13, 14};
__constant__ int c_tiler[NTILES]  = {0,128,256, 0,128,256, 0,128, 0,128, 0,128, 0,128, 0,0,0,0,0,0,0,0,0};

// Preconverted block matrices (fp16, zero K-padding), zero-initialized.
__device__ __half g_A[450560];

struct MatPtrs { const float* p[NGROUPS]; };

// ---------------- PTX helpers (compute_103-legal) ----------------
__device__ __forceinline__ uint32_t smem_u32(const void* p) {
    uint32_t a;
    asm("{ .reg .u64 t; cvta.to.shared.u64 t, %1; cvt.u32.u64 %0, t; }" : "=r"(a) : "l"(p));
    return a;
}
__device__ __forceinline__ void cp16(uint32_t dst, const void* src) {
    asm volatile("cp.async.cg.shared.global [%0], [%1], 16;" :: "r"(dst), "l"(src));
}
#define CP_COMMIT() asm volatile("cp.async.commit_group;" ::: "memory")
#define CP_WAIT1()  asm volatile("cp.async.wait_group 1;" ::: "memory")
#define CP_WAIT0()  asm volatile("cp.async.wait_group 0;" ::: "memory")

__device__ __forceinline__ void ldsm_x4(uint32_t* r, uint32_t addr) {
    asm volatile("ldmatrix.sync.aligned.m8n8.x4.shared.b16 {%0,%1,%2,%3}, [%4];"
        : "=r"(r[0]), "=r"(r[1]), "=r"(r[2]), "=r"(r[3]) : "r"(addr));
}
__device__ __forceinline__ void ldsm_x4_t(uint32_t* r, uint32_t addr) {
    asm volatile("ldmatrix.sync.aligned.m8n8.x4.trans.shared.b16 {%0,%1,%2,%3}, [%4];"
        : "=r"(r[0]), "=r"(r[1]), "=r"(r[2]), "=r"(r[3]) : "r"(addr));
}
__device__ __forceinline__ void mma_f16(float* c, const uint32_t* a, uint32_t b0, uint32_t b1) {
    asm volatile("mma.sync.aligned.m16n8k16.row.col.f32.f16.f16.f32 "
        "{%0,%1,%2,%3}, {%4,%5,%6,%7}, {%8,%9}, {%0,%1,%2,%3};"
        : "+f"(c[0]), "+f"(c[1]), "+f"(c[2]), "+f"(c[3])
        : "r"(a[0]), "r"(a[1]), "r"(a[2]), "r"(a[3]), "r"(b0), "r"(b1));
}

// ---------------- prep: round mats to fp16 (K zero-padded) ----------------
__global__ void conv_mats_kernel(MatPtrs mats) {
    const int idx = blockIdx.x * 256 + threadIdx.x;
    if (idx >= 450560) return;
    int g = 0;
    #pragma unroll
    for (int i = 1; i < NGROUPS; i++) if (idx >= c_aoff[i]) g = i;
    const int local = idx - c_aoff[g];
    const int Kp = c_kpad[g], G = c_g[g];
    const int m = local / Kp;
    const int k = local - m * Kp;
    float v = (k < G) ? mats.p[g][m * G + k] : 0.0f;
    g_A[idx] = __float2half_rn(v);
}

// ---------------- main fp16 HMMA kernel ----------------
#define APITCH 72    // fp16: 64 k + 8 pad  -> 144B rows (conflict-free)
#define BPITCH 136   // fp16: 128 n + 8 pad -> 272B rows (conflict-free)
#define OFF_A  0
#define OFF_B  18432                   // 128 * 144
#define STAGE_BYTES 35840              // 18432 + 64*272
#define SMEM_TOTAL  (2 * STAGE_BYTES)  // 71680 -> 2 CTAs/SM

__global__ __launch_bounds__(256, 2)
void bdiag_hmma_kernel(const float* __restrict__ x, float* __restrict__ out)
{
    extern __shared__ char smem[];
    const uint32_t sb = smem_u32(smem);

    const int tid    = threadIdx.x;
    const int lane   = tid & 31;
    const int wid    = tid >> 5;
    const int warp_m = wid >> 1;   // 4 warps over M (128 rows, 32 each)
    const int warp_n = wid & 1;    // 2 warps over N (128 cols, 64 each)

    const int tile  = blockIdx.y;
    const int grp   = c_tileg[tile];
    const int K     = c_g[grp];
    const int Kpad  = c_kpad[grp];
    const int row0  = c_tiler[tile];
    const int col0  = blockIdx.x * 128;
    const int xbase = c_start[grp];

    const __half* __restrict__ Ag = g_A + c_aoff[grp];

    // A cp.async ownership: 1024 slots (128 rows x 8 segs of 16B), 4/thread.
    const int a_seg = tid & 7;
    const int a_r0  = tid >> 3;    // + j*32
    #pragma unroll
    for (int j = 0; j < 4; j++) {
        if (row0 + a_r0 + j * 32 >= K) {   // zero-prefill masked rows, both stages
            const uint32_t d = (a_r0 + j * 32) * 144 + a_seg * 16;
            const uint4 z = make_uint4(0, 0, 0, 0);
            *reinterpret_cast<uint4*>(smem + d + OFF_A) = z;
            *reinterpret_cast<uint4*>(smem + d + STAGE_BYTES + OFF_A) = z;
        }
    }

    // B ownership: 8 slots/thread; slot idx = tid + j*256; k = idx>>5, c4 = idx&31
    const int b_k0 = tid >> 5;      // + j*8
    const int b_c4 = tid & 31;
    const int nch  = Kpad >> 6;

    auto issueA = [&](int ch, uint32_t sbuf) {
        const int kc0 = ch << 6;
        #pragma unroll
        for (int j = 0; j < 4; j++) {
            const int rr = a_r0 + j * 32;
            if (row0 + rr < K)
                cp16(sbuf + rr * 144 + a_seg * 16 + OFF_A,
                     Ag + (size_t)(row0 + rr) * Kpad + kc0 + a_seg * 8);
        }
    };
    // Inline B load+convert+store (short-lived temps, MLP=2)
    auto convLoadB = [&](int ch, uint32_t off) {
        const int kc0 = ch << 6;
        #pragma unroll
        for (int jj = 0; jj < 4; jj++) {
            float4 v0 = make_float4(0.f, 0.f, 0.f, 0.f), v1 = v0;
            const int k0 = b_k0 + (jj * 2) * 8;
            const int k1 = b_k0 + (jj * 2 + 1) * 8;
            if (kc0 + k0 < K)
                v0 = *reinterpret_cast<const float4*>(
                    x + (size_t)(xbase + kc0 + k0) * NCOLS + col0 + b_c4 * 4);
            if (kc0 + k1 < K)
                v1 = *reinterpret_cast<const float4*>(
                    x + (size_t)(xbase + kc0 + k1) * NCOLS + col0 + b_c4 * 4);
            __half2 a01 = __floats2half2_rn(v0.x, v0.y);
            __half2 a23 = __floats2half2_rn(v0.z, v0.w);
            __half2 b01 = __floats2half2_rn(v1.x, v1.y);
            __half2 b23 = __floats2half2_rn(v1.z, v1.w);
            uint2 ua, ub;
            ua.x = *reinterpret_cast<uint32_t*>(&a01);
            ua.y = *reinterpret_cast<uint32_t*>(&a23);
            ub.x = *reinterpret_cast<uint32_t*>(&b01);
            ub.y = *reinterpret_cast<uint32_t*>(&b23);
            *reinterpret_cast<uint2*>(smem + off + OFF_B + k0 * 272 + b_c4 * 8) = ua;
            *reinterpret_cast<uint2*>(smem + off + OFF_B + k1 * 272 + b_c4 * 8) = ub;
        }
    };

    float acc[2][8][4];
    #pragma unroll
    for (int mi = 0; mi < 2; mi++)
        #pragma unroll
        for (int ni = 0; ni < 8; ni++)
            #pragma unroll
            for (int q = 0; q < 4; q++) acc[mi][ni][q] = 0.0f;

    const int lr = lane & 15;
    const int lc = lane >> 4;

    // ---- prologue: stage 0 (A async, B inline)
    issueA(0, sb);
    CP_COMMIT();
    convLoadB(0, 0);

    for (int ch = 0; ch < nch; ch++) {
        if (ch + 1 < nch) {
            issueA(ch + 1, sb + ((ch + 1) & 1) * STAGE_BYTES);
            CP_COMMIT();
            CP_WAIT1();      // A(ch) landed (in-order group completion)
        } else {
            CP_WAIT0();      // last chunk: drain everything
        }
        __syncthreads();     // stage ch fully visible (A async + B STS)

        const uint32_t sbase = sb + (ch & 1) * STAGE_BYTES;
        #pragma unroll
        for (int ks = 0; ks < 4; ks++) {
            uint32_t af[2][4];
            #pragma unroll
            for (int mi = 0; mi < 2; mi++) {
                const uint32_t ao = sbase + OFF_A +
                    ((warp_m * 32 + mi * 16 + lr) * APITCH + ks * 16 + lc * 8) * 2;
                ldsm_x4(af[mi], ao);
            }
            uint32_t bf[4][4];
            #pragma unroll
            for (int p = 0; p < 4; p++) {
                const uint32_t bo = sbase + OFF_B +
                    ((ks * 16 + lr) * BPITCH + warp_n * 64 + p * 16 + lc * 8) * 2;
                ldsm_x4_t(bf[p], bo);
            }
            #pragma unroll
            for (int mi = 0; mi < 2; mi++)
                #pragma unroll
                for (int ni = 0; ni < 8; ni++) {
                    const int p = ni >> 1, s = (ni & 1) * 2;
                    mma_f16(acc[mi][ni], af[mi], bf[p][s], bf[p][s + 1]);
                }
        }

        // inline load+convert next chunk's B into the other stage
        if (ch + 1 < nch) convLoadB(ch + 1, ((ch + 1) & 1) * STAGE_BYTES);

        __syncthreads();     // stage reads done + next-stage B STS ordered
    }

    // ---- epilogue: masked float2 stores straight from fragments
    const int rbase = row0 + warp_m * 32 + (lane >> 2);
    const int cb    = col0 + warp_n * 64 + (lane & 3) * 2;
    #pragma unroll
    for (int mi = 0; mi < 2; mi++) {
        #pragma unroll
        for (int half = 0; half < 2; half++) {
            const int row = rbase + mi * 16 + half * 8;
            if (row < K) {
                float* dst = out + (size_t)(xbase + row) * NCOLS + cb;
                #pragma unroll
                for (int ni = 0; ni < 8; ni++)
                    *reinterpret_cast<float2*>(dst + ni * 8) =
                        make_float2(acc[mi][ni][half * 2], acc[mi][ni][half * 2 + 1]);
            }
        }
    }
}

extern "C" void kernel_launch(void* const* d_in, const int* in_sizes, int n_in,
                              void* d_out, int out_size)
{
    const float* x = (const float*)d_in[0];
    float* out = (float*)d_out;

    MatPtrs mats;
    for (int i = 0; i < NGROUPS; i++) mats.p[i] = (const float*)d_in[1 + i];

    cudaFuncSetAttribute(bdiag_hmma_kernel,
                         cudaFuncAttributeMaxDynamicSharedMemorySize, SMEM_TOTAL);

    conv_mats_kernel<<<1760, 256>>>(mats);
    bdiag_hmma_kernel<<<dim3(NCOLS / 128, NTILES), 256, SMEM_TOTAL>>>(x, out);
}